// round 11
// baseline (speedup 1.0000x reference)
#include <cuda_runtime.h>
#include <cuda_bf16.h>
#include <cstdint>

#define BB 128
#define LL 256
#define HH 1024
#define TT 9

#define NCH 12
#define CHS 22                 // 12*22 = 264 >= 256

#define TPB 256
#define GRID 296               // 148 SMs x 2 blocks
#define NTILES 1024            // 32-row tiles (8 per batch)

// Scratch (no allocations allowed)
__device__ __align__(16) float g_emis[BB * LL * TT];
__device__ float g_llh[BB];
__device__ int g_ctr;          // self-resetting
__device__ int g_done[BB];     // per-batch tile counters, self-resetting

#define FFMA2(acc, a, b) \
    asm("fma.rn.f32x2 %0, %1, %2, %0;" : "+l"(acc) : "l"(a), "l"(b))
#define CP16(dst, src) \
    asm volatile("cp.async.cg.shared.global [%0], [%1], 16;" :: "r"(dst), "l"(src))
#define CPC() asm volatile("cp.async.commit_group;" ::: "memory")
#define CPW(n) asm volatile("cp.async.wait_group %0;" :: "n"(n) : "memory")

// Dynamic smem layout (floats):
//   Ws    : [0, 9216)                  36 KB  (persists whole kernel)
//   hbuf  : [9216, 25600)              64 KB  (4 ring slots x 4096 floats)
//   CRF region ALIASES hbuf (pipeline fully drained before CRF):
//     u_s  = 9216      (256*12)
//     tr_s = 12288     (81)
//     Et_s = 12369     (81)
//     st_s = 12450     (9)
//     en_s = 12459     (9)
//     nr_s = 12468     (8)
//     lab_s= 12476     (256 ints)
//     P_s  = 12732     (12*81)
//     e_s  = 13704     (108 ints)
#define SMEM_FLOATS 25600

__global__ __launch_bounds__(TPB, 2) void fused_kernel(
    const float* __restrict__ hidden,
    const float* __restrict__ W,
    const float* __restrict__ bias,
    const float* __restrict__ start_t,
    const float* __restrict__ end_t,
    const float* __restrict__ trans,
    const int*   __restrict__ labels,
    const int*   __restrict__ lengths,
    float* __restrict__ out)
{
    extern __shared__ __align__(16) float sm[];
    float* Ws   = sm;
    float* hbuf = sm + 9216;
    float* u_s  = sm + 9216;
    float* tr_s = sm + 12288;
    float* Et_s = sm + 12369;
    float* st_s = sm + 12450;
    float* en_s = sm + 12459;
    float* nr_s = sm + 12468;
    int*   lab_s = (int*)(sm + 12476);
    float* P_s  = sm + 12732;
    int*   e_s  = (int*)(sm + 13704);
    __shared__ float bs[TT];
    __shared__ int trig_s;

    int tid = threadIdx.x;
    int lane = tid & 31;
    int w = tid >> 5;

    // ---- load W (36 KB) + bias into smem once ----
    {
        const float4* W4 = reinterpret_cast<const float4*>(W);
        float4* Ws4 = reinterpret_cast<float4*>(Ws);
#pragma unroll
        for (int i = 0; i < 9; i++) Ws4[tid + i * TPB] = W4[tid + i * TPB];
        if (tid < TT) bs[tid] = bias[tid];
    }
    __syncthreads();

    uint32_t hb = (uint32_t)__cvta_generic_to_shared(hbuf);
    const ulonglong2* Ws2 = reinterpret_cast<const ulonglong2*>(Ws);

    for (int tile = blockIdx.x; tile < NTILES; tile += GRID) {
        const char* hbase =
            (const char*)hidden + (size_t)tile * 32 * HH * sizeof(float);

        unsigned long long acc[4][TT];
#pragma unroll
        for (int m = 0; m < 4; m++)
#pragma unroll
            for (int t = 0; t < TT; t++) acc[m][t] = 0ull;

        // ---- prologue: issue stages 0..3 (ring of 4, 16 KB each) ----
#pragma unroll
        for (int s = 0; s < 4; s++) {
#pragma unroll
            for (int q = 0; q < 4; q++) {
                int u = tid + q * TPB;       // 0..1023 : 16B unit in stage
                int r = u >> 5, ku = u & 31; // row, k-unit
                CP16(hb + (s & 3) * 16384 + u * 16,
                     hbase + (size_t)r * 4096 + (size_t)s * 512 + ku * 16);
            }
            CPC();
        }

        // ---- 8 stages: consume + refill ----
#pragma unroll
        for (int s = 0; s < 8; s++) {
            if (s < 5) { CPW(3); } else if (s == 5) { CPW(2); }
            else if (s == 6) { CPW(1); } else { CPW(0); }
            __syncthreads();

            const ulonglong2* hs2 =
                reinterpret_cast<const ulonglong2*>(hbuf + (s & 3) * 4096);
            ulonglong2 h0 = hs2[(w * 4 + 0) * 32 + lane];
            ulonglong2 h1 = hs2[(w * 4 + 1) * 32 + lane];
            ulonglong2 h2 = hs2[(w * 4 + 2) * 32 + lane];
            ulonglong2 h3 = hs2[(w * 4 + 3) * 32 + lane];
#pragma unroll
            for (int t = 0; t < TT; t++) {
                ulonglong2 wv = Ws2[t * 256 + s * 32 + lane];
                FFMA2(acc[0][t], h0.x, wv.x);
                FFMA2(acc[0][t], h0.y, wv.y);
                FFMA2(acc[1][t], h1.x, wv.x);
                FFMA2(acc[1][t], h1.y, wv.y);
                FFMA2(acc[2][t], h2.x, wv.x);
                FFMA2(acc[2][t], h2.y, wv.y);
                FFMA2(acc[3][t], h3.x, wv.x);
                FFMA2(acc[3][t], h3.y, wv.y);
            }
            __syncthreads();

            if (s < 4) {  // refill same slot with stage s+4
                int s2 = s + 4;
#pragma unroll
                for (int q = 0; q < 4; q++) {
                    int u = tid + q * TPB;
                    int r = u >> 5, ku = u & 31;
                    CP16(hb + (s & 3) * 16384 + u * 16,
                         hbase + (size_t)r * 4096 + (size_t)s2 * 512 + ku * 16);
                }
                CPC();
            }
        }

        // ---- epilogue: serialized butterfly, minimal live regs ----
        int row0g = tile * 32 + w * 4;
#pragma unroll
        for (int m = 0; m < 4; m++) {
            float resm;
#pragma unroll
            for (int t = 0; t < TT; t++) {
                float lo, hi;
                asm("mov.b64 {%0,%1}, %2;" : "=f"(lo), "=f"(hi) : "l"(acc[m][t]));
                float v = lo + hi;
#pragma unroll
                for (int off = 16; off > 0; off >>= 1)
                    v += __shfl_xor_sync(0xffffffffu, v, off);
                if (lane == t) resm = v + bs[t];
            }
            if (lane < TT)
                g_emis[(size_t)(row0g + m) * TT + lane] = resm;
        }

        // ---- per-batch completion → inline CRF ----
        __threadfence();
        __syncthreads();
        int b = tile >> 3;
        if (tid == 0) {
            int old = atomicAdd(&g_done[b], 1);
            trig_s = (old == 7);
            if (old == 7) g_done[b] = 0;  // self-reset for graph replay
        }
        __syncthreads();

        if (trig_s) {
            __threadfence();  // acquire: see all blocks' g_emis writes
            const float* em = g_emis + (size_t)b * LL * TT;

            // loads: u = exp(em) (stride-12), labels, trans(+exp), st/en
            for (int i = tid; i < LL * TT; i += TPB) {
                int t = i / TT, k = i - t * TT;
                u_s[t * 12 + k] = __expf(em[i]);
            }
            if (tid < LL / 4)
                reinterpret_cast<int4*>(lab_s)[tid] =
                    reinterpret_cast<const int4*>(labels + (size_t)b * LL)[tid];
            if (tid < TT * TT) {
                float tv = trans[tid];
                tr_s[tid] = tv;
                Et_s[tid] = __expf(tv);
            }
            if (tid < TT) { st_s[tid] = start_t[tid]; en_s[tid] = end_t[tid]; }
            int len = lengths[b];
            __syncthreads();

            // numerator partials (em gathered from L2)
            float num_p = 0.0f;
            for (int t = 1 + tid; t < len; t += TPB) {
                int pv = lab_s[t - 1], cu = lab_s[t];
                num_p += tr_s[pv * TT + cu] + em[t * TT + cu];
            }
#pragma unroll
            for (int off = 16; off > 0; off >>= 1)
                num_p += __shfl_xor_sync(0xffffffffu, num_p, off);
            if (lane == 0) nr_s[w] = num_p;

            // chunked column scan: task = (chunk c, column j), 108 tasks
            if (tid < NCH * TT) {
                int c = tid / TT;
                int j = tid - c * TT;
                int lo = (c == 0) ? 1 : CHS * c;
                int hi = min(CHS * (c + 1), len);

                float P[TT];
#pragma unroll
                for (int k = 0; k < TT; k++) P[k] = (k == j) ? 1.0f : 0.0f;
                int esum = 0;

                for (int t = hi - 1; t >= lo; t--) {
                    float4 ua = *reinterpret_cast<const float4*>(&u_s[t * 12]);
                    float4 ub = *reinterpret_cast<const float4*>(&u_s[t * 12 + 4]);
                    float u8 = u_s[t * 12 + 8];
                    float wv[TT];
                    wv[0] = ua.x * P[0]; wv[1] = ua.y * P[1]; wv[2] = ua.z * P[2];
                    wv[3] = ua.w * P[3]; wv[4] = ub.x * P[4]; wv[5] = ub.y * P[5];
                    wv[6] = ub.z * P[6]; wv[7] = ub.w * P[7]; wv[8] = u8   * P[8];
                    float np[TT];
#pragma unroll
                    for (int i = 0; i < TT; i++) {
                        float s = Et_s[i * TT] * wv[0];
#pragma unroll
                        for (int k = 1; k < TT; k++) s += Et_s[i * TT + k] * wv[k];
                        np[i] = s;
                    }
#pragma unroll
                    for (int i = 0; i < TT; i++) P[i] = np[i];

                    if (((hi - t) & 3) == 0) {
                        int e = (__float_as_int(P[0]) >> 23) & 255;
                        float rr = __int_as_float((254 - e) << 23);  // exact
                        esum += e - 127;
#pragma unroll
                        for (int i = 0; i < TT; i++) P[i] *= rr;
                    }
                }
#pragma unroll
                for (int k = 0; k < TT; k++) P_s[c * 81 + k * TT + j] = P[k];
                e_s[c * TT + j] = esum;
            }
            __syncthreads();

            // combine (warp 0, lane-parallel over columns)
            if (w == 0) {
                float v[TT];
                int G = 0;
#pragma unroll
                for (int k = 0; k < TT; k++) v[k] = __expf(st_s[k] + em[k]);

                int jj = (lane < TT) ? lane : 0;
#pragma unroll
                for (int c = 0; c < NCH; c++) {
                    float s = v[0] * P_s[c * 81 + jj];
#pragma unroll
                    for (int k = 1; k < TT; k++)
                        s += v[k] * P_s[c * 81 + k * TT + jj];

                    float nv[TT];
#pragma unroll
                    for (int k = 0; k < TT; k++)
                        nv[k] = __shfl_sync(0xffffffffu, s, k);

                    int ec[TT];
#pragma unroll
                    for (int k = 0; k < TT; k++) ec[k] = e_s[c * TT + k];

                    int Tk[TT], Tmax;
#pragma unroll
                    for (int k = 0; k < TT; k++)
                        Tk[k] = G + ec[k] + ((__float_as_int(nv[k]) >> 23) & 255);
                    Tmax = Tk[0];
#pragma unroll
                    for (int k = 1; k < TT; k++) Tmax = max(Tmax, Tk[k]);
                    int Gnew = Tmax - 127;
#pragma unroll
                    for (int k = 0; k < TT; k++) {
                        int d = G + ec[k] - Gnew;
                        v[k] = (d < -126) ? 0.0f
                                          : nv[k] * __int_as_float((127 + d) << 23);
                    }
                    G = Gnew;
                }

                float tot = 0.0f;
#pragma unroll
                for (int k = 0; k < TT; k++) tot += v[k] * __expf(en_s[k]);
                float denom = __logf(tot) + (float)G * 0.6931471805599453f;

                float ns = (lane < 8) ? nr_s[lane] : 0.0f;
#pragma unroll
                for (int off = 4; off > 0; off >>= 1)
                    ns += __shfl_xor_sync(0xffffffffu, ns, off);
                ns = __shfl_sync(0xffffffffu, ns, 0);
                int tag0 = lab_s[0];
                float num = ns + st_s[tag0] + em[tag0] + en_s[lab_s[len - 1]];

                if (lane == 0) g_llh[b] = num - denom;

                // fused finalization: last batch computes -mean(llh)
                __threadfence();
                __syncwarp();
                int last = 0;
                if (lane == 0) {
                    int old = atomicAdd(&g_ctr, 1);
                    last = (old == BB - 1);
                }
                last = __shfl_sync(0xffffffffu, last, 0);
                if (last) {
                    __threadfence();
                    float vv = 0.0f;
#pragma unroll
                    for (int i = 0; i < BB / 32; i++) vv += g_llh[lane + 32 * i];
#pragma unroll
                    for (int off = 16; off > 0; off >>= 1)
                        vv += __shfl_xor_sync(0xffffffffu, vv, off);
                    if (lane == 0) {
                        out[0] = -vv * (1.0f / (float)BB);
                        g_ctr = 0;  // self-reset for graph replay
                    }
                }
            }
            __syncthreads();  // CRF smem region free before hbuf reuse
        }
    }
}

extern "C" void kernel_launch(void* const* d_in, const int* in_sizes, int n_in,
                              void* d_out, int out_size)
{
    const float* hidden  = (const float*)d_in[0];
    const float* W       = (const float*)d_in[1];
    const float* bias    = (const float*)d_in[2];
    const float* start_t = (const float*)d_in[3];
    const float* end_t   = (const float*)d_in[4];
    const float* trans   = (const float*)d_in[5];
    const int*   labels  = (const int*)d_in[6];
    const int*   lengths = (const int*)d_in[7];
    float* out = (float*)d_out;

    cudaFuncSetAttribute(fused_kernel,
                         cudaFuncAttributeMaxDynamicSharedMemorySize,
                         SMEM_FLOATS * sizeof(float));
    fused_kernel<<<GRID, TPB, SMEM_FLOATS * sizeof(float)>>>(
        hidden, W, bias, start_t, end_t, trans, labels, lengths, out);
}

// round 12
// speedup vs baseline: 2.0332x; 2.0332x over previous
#include <cuda_runtime.h>
#include <cuda_bf16.h>
#include <cstdint>

#define BB 128
#define LL 256
#define HH 1024
#define TT 9

#define NCH 12
#define CHS 22                    // 12*22 = 264 >= 256

#define TPB 256
#define EMIS_GRID 296             // 148 SMs x 2 blocks
#define NW (EMIS_GRID * 8)        // total warps = 2368
#define NSTRIPS (BB * LL / 4)     // 8192 strips of 4 rows

// Scratch (no allocations allowed)
__device__ __align__(16) float g_emis[BB * LL * TT];
__device__ float g_llh[BB];
__device__ int g_ctr;

#define FFMA2(acc, a, b) \
    asm("fma.rn.f32x2 %0, %1, %2, %0;" : "+l"(acc) : "l"(a), "l"(b))
#define CP16(dst, src) \
    asm volatile("cp.async.cg.shared.global [%0], [%1], 16;" :: "r"(dst), "l"(src))
#define CPC() asm volatile("cp.async.commit_group;" ::: "memory")
#define CPW3() asm volatile("cp.async.wait_group 3;" ::: "memory")

// Dynamic smem (floats): Ws [0,9216) = 36KB ; ring [9216, 9216+16384) = 64KB
// ring: 8 warps x 4 slots x 512 floats (slot = 4 rows x 128 floats = 2KB)
#define SMEM_FLOATS (9216 + 16384)

// ---------------------------------------------------------------------------
// Kernel 1: emissions = hidden @ W^T + b.
// Per-warp cp.async ring (4 slots, always 3 stages in flight, no block
// barriers in the mainloop). 4 rows/warp, packed FFMA2, serialized epilogue.
// ---------------------------------------------------------------------------
__global__ __launch_bounds__(TPB, 2) void emis_kernel(
    const float* __restrict__ hidden,
    const float* __restrict__ W,
    const float* __restrict__ bias)
{
    extern __shared__ __align__(16) float sm[];
    float* Ws = sm;
    float* ring = sm + 9216;
    __shared__ float bs[TT];

    int tid = threadIdx.x;
    int lane = tid & 31;
    int w = tid >> 5;

    {
        const float4* W4 = reinterpret_cast<const float4*>(W);
        float4* Ws4 = reinterpret_cast<float4*>(Ws);
#pragma unroll
        for (int i = 0; i < 9; i++) Ws4[tid + i * TPB] = W4[tid + i * TPB];
        if (tid < TT) bs[tid] = bias[tid];
    }
    __syncthreads();

    const ulonglong2* Ws2 = reinterpret_cast<const ulonglong2*>(Ws);
    float* myring = ring + w * 2048;                  // 4 slots x 512 floats
    uint32_t rb = (uint32_t)__cvta_generic_to_shared(myring);
    int gwid = blockIdx.x * 8 + w;

    // issue one stage (4 rows x 512B) into slot stage&3; always commit
    auto issue = [&](int st, int stage) {
        if (st < NSTRIPS) {
            const char* src = (const char*)hidden +
                ((size_t)st * 4 * HH + (size_t)stage * 128 + lane * 4) * 4;
            uint32_t dst = rb + (stage & 3) * 2048 + lane * 16;
#pragma unroll
            for (int q = 0; q < 4; q++)
                CP16(dst + q * 512, src + (size_t)q * HH * 4);
        }
        CPC();
    };

    // prologue: stages 0..3 of first strip
#pragma unroll
    for (int s = 0; s < 4; s++) issue(gwid, s);

    for (int strip = gwid; strip < NSTRIPS; strip += NW) {
        int nstrip = strip + NW;

        unsigned long long acc[4][TT];
#pragma unroll
        for (int m = 0; m < 4; m++)
#pragma unroll
            for (int t = 0; t < TT; t++) acc[m][t] = 0ull;

#pragma unroll
        for (int i = 0; i < 8; i++) {
            CPW3();  // stage i's group complete (one group per stage, 4 ahead)
            const ulonglong2* hs2 =
                reinterpret_cast<const ulonglong2*>(myring + (i & 3) * 512);
            ulonglong2 h0 = hs2[0 * 32 + lane];
            ulonglong2 h1 = hs2[1 * 32 + lane];
            ulonglong2 h2 = hs2[2 * 32 + lane];
            ulonglong2 h3 = hs2[3 * 32 + lane];
#pragma unroll
            for (int t = 0; t < TT; t++) {
                ulonglong2 wv = Ws2[t * 256 + i * 32 + lane];
                FFMA2(acc[0][t], h0.x, wv.x);
                FFMA2(acc[0][t], h0.y, wv.y);
                FFMA2(acc[1][t], h1.x, wv.x);
                FFMA2(acc[1][t], h1.y, wv.y);
                FFMA2(acc[2][t], h2.x, wv.x);
                FFMA2(acc[2][t], h2.y, wv.y);
                FFMA2(acc[3][t], h3.x, wv.x);
                FFMA2(acc[3][t], h3.y, wv.y);
            }
            // refill the slot just consumed: stage i+4 (this strip) or
            // stage i-4 of the next strip; empty commit past the end.
            if (i < 4) issue(strip, i + 4);
            else       issue(nstrip, i - 4);
        }

        // serialized epilogue: minimal live registers
#pragma unroll
        for (int m = 0; m < 4; m++) {
            float resm;
#pragma unroll
            for (int t = 0; t < TT; t++) {
                float lo, hi;
                asm("mov.b64 {%0,%1}, %2;" : "=f"(lo), "=f"(hi) : "l"(acc[m][t]));
                float v = lo + hi;
#pragma unroll
                for (int off = 16; off > 0; off >>= 1)
                    v += __shfl_xor_sync(0xffffffffu, v, off);
                if (lane == t) resm = v + bs[t];
            }
            if (lane < TT)
                g_emis[(size_t)(strip * 4 + m) * TT + lane] = resm;  // 36B run
        }
    }
}

// ---------------------------------------------------------------------------
// Kernel 2: chunk-parallel CRF forward (R10 structure, unchanged).
// ---------------------------------------------------------------------------
__global__ void crf_kernel(
    const float* __restrict__ start_t,
    const float* __restrict__ end_t,
    const float* __restrict__ trans,
    const int*   __restrict__ labels,
    const int*   __restrict__ lengths,
    float* __restrict__ out)
{
    __shared__ __align__(16) float em_s[LL * TT];
    __shared__ __align__(16) float u_s[LL * 12];
    __shared__ float tr_s[TT * TT];
    __shared__ float Etr_s[TT * TT];
    __shared__ float st_s[TT];
    __shared__ float en_s[TT];
    __shared__ __align__(16) int lab_s[LL];
    __shared__ float P_s[NCH][TT][TT];
    __shared__ int   e_s[NCH][TT];
    __shared__ float num_red[8];

    int b = blockIdx.x;
    int tid = threadIdx.x;
    int lane = tid & 31;
    int w = tid >> 5;

    {
        const float4* src = reinterpret_cast<const float4*>(g_emis + (size_t)b * LL * TT);
        float4* dst = reinterpret_cast<float4*>(em_s);
        for (int i = tid; i < LL * TT / 4; i += 256) dst[i] = src[i];
    }
    if (tid < LL / 4)
        reinterpret_cast<int4*>(lab_s)[tid] =
            reinterpret_cast<const int4*>(labels + (size_t)b * LL)[tid];
    if (tid < TT * TT) {
        float tv = trans[tid];
        tr_s[tid] = tv;
        Etr_s[tid] = __expf(tv);
    }
    if (tid < TT) { st_s[tid] = start_t[tid]; en_s[tid] = end_t[tid]; }
    int len = lengths[b];
    __syncthreads();

    for (int i = tid; i < LL * TT; i += 256) {
        int t = i / TT, k = i - t * TT;
        u_s[t * 12 + k] = __expf(em_s[i]);
    }
    float num_p = 0.0f;
    for (int t = 1 + tid; t < len; t += 256) {
        int pv = lab_s[t - 1], cu = lab_s[t];
        num_p += tr_s[pv * TT + cu] + em_s[t * TT + cu];
    }
#pragma unroll
    for (int off = 16; off > 0; off >>= 1)
        num_p += __shfl_xor_sync(0xffffffffu, num_p, off);
    if (lane == 0) num_red[w] = num_p;
    __syncthreads();

    int task = w * 32 + lane;
    if (task < NCH * TT) {
        int c = task / TT;
        int j = task - c * TT;
        int lo = (c == 0) ? 1 : CHS * c;
        int hi = min(CHS * (c + 1), len);

        float E[TT * TT];
#pragma unroll
        for (int i = 0; i < TT * TT; i++) E[i] = Etr_s[i];

        float P[TT];
#pragma unroll
        for (int k = 0; k < TT; k++) P[k] = (k == j) ? 1.0f : 0.0f;
        int esum = 0;

        for (int t = hi - 1; t >= lo; t--) {
            float4 ua = *reinterpret_cast<const float4*>(&u_s[t * 12]);
            float4 ub = *reinterpret_cast<const float4*>(&u_s[t * 12 + 4]);
            float u8 = u_s[t * 12 + 8];
            float wv[TT];
            wv[0] = ua.x * P[0]; wv[1] = ua.y * P[1]; wv[2] = ua.z * P[2];
            wv[3] = ua.w * P[3]; wv[4] = ub.x * P[4]; wv[5] = ub.y * P[5];
            wv[6] = ub.z * P[6]; wv[7] = ub.w * P[7]; wv[8] = u8   * P[8];
            float np[TT];
#pragma unroll
            for (int i = 0; i < TT; i++) {
                float s = E[i * TT] * wv[0];
#pragma unroll
                for (int k = 1; k < TT; k++) s += E[i * TT + k] * wv[k];
                np[i] = s;
            }
#pragma unroll
            for (int i = 0; i < TT; i++) P[i] = np[i];

            if (((hi - t) & 3) == 0) {
                int e = (__float_as_int(P[0]) >> 23) & 255;
                float rr = __int_as_float((254 - e) << 23);  // exact 2^(127-e)
                esum += e - 127;
#pragma unroll
                for (int i = 0; i < TT; i++) P[i] *= rr;
            }
        }
#pragma unroll
        for (int k = 0; k < TT; k++) P_s[c][k][j] = P[k];
        e_s[c][j] = esum;
    }
    __syncthreads();

    if (w == 0) {
        float v[TT];
        int G = 0;
#pragma unroll
        for (int k = 0; k < TT; k++) v[k] = __expf(st_s[k] + em_s[k]);

        int jj = (lane < TT) ? lane : 0;
#pragma unroll
        for (int c = 0; c < NCH; c++) {
            float s = v[0] * P_s[c][0][jj];
#pragma unroll
            for (int k = 1; k < TT; k++) s += v[k] * P_s[c][k][jj];

            float nv[TT];
#pragma unroll
            for (int k = 0; k < TT; k++) nv[k] = __shfl_sync(0xffffffffu, s, k);

            int ec[TT];
#pragma unroll
            for (int k = 0; k < TT; k++) ec[k] = e_s[c][k];

            int Tk[TT], Tmax;
#pragma unroll
            for (int k = 0; k < TT; k++)
                Tk[k] = G + ec[k] + ((__float_as_int(nv[k]) >> 23) & 255);
            Tmax = Tk[0];
#pragma unroll
            for (int k = 1; k < TT; k++) Tmax = max(Tmax, Tk[k]);
            int Gnew = Tmax - 127;
#pragma unroll
            for (int k = 0; k < TT; k++) {
                int d = G + ec[k] - Gnew;
                v[k] = (d < -126) ? 0.0f : nv[k] * __int_as_float((127 + d) << 23);
            }
            G = Gnew;
        }

        float tot = 0.0f;
#pragma unroll
        for (int k = 0; k < TT; k++) tot += v[k] * __expf(en_s[k]);
        float denom = __logf(tot) + (float)G * 0.6931471805599453f;

        float ns = (lane < 8) ? num_red[lane] : 0.0f;
#pragma unroll
        for (int off = 4; off > 0; off >>= 1)
            ns += __shfl_xor_sync(0xffffffffu, ns, off);
        ns = __shfl_sync(0xffffffffu, ns, 0);
        int tag0 = lab_s[0];
        float num = ns + st_s[tag0] + em_s[tag0] + en_s[lab_s[len - 1]];

        if (lane == 0) g_llh[b] = num - denom;

        __threadfence();
        __syncwarp();
        int last = 0;
        if (lane == 0) {
            int old = atomicAdd(&g_ctr, 1);
            last = (old == BB - 1);
        }
        last = __shfl_sync(0xffffffffu, last, 0);
        if (last) {
            __threadfence();
            float vv = 0.0f;
#pragma unroll
            for (int i = 0; i < BB / 32; i++) vv += g_llh[lane + 32 * i];
#pragma unroll
            for (int off = 16; off > 0; off >>= 1)
                vv += __shfl_xor_sync(0xffffffffu, vv, off);
            if (lane == 0) {
                out[0] = -vv * (1.0f / (float)BB);
                g_ctr = 0;  // self-reset for graph replay
            }
        }
    }
}

extern "C" void kernel_launch(void* const* d_in, const int* in_sizes, int n_in,
                              void* d_out, int out_size)
{
    const float* hidden  = (const float*)d_in[0];
    const float* W       = (const float*)d_in[1];
    const float* bias    = (const float*)d_in[2];
    const float* start_t = (const float*)d_in[3];
    const float* end_t   = (const float*)d_in[4];
    const float* trans   = (const float*)d_in[5];
    const int*   labels  = (const int*)d_in[6];
    const int*   lengths = (const int*)d_in[7];
    float* out = (float*)d_out;

    cudaFuncSetAttribute(emis_kernel,
                         cudaFuncAttributeMaxDynamicSharedMemorySize,
                         SMEM_FLOATS * sizeof(float));
    emis_kernel<<<EMIS_GRID, TPB, SMEM_FLOATS * sizeof(float)>>>(hidden, W, bias);
    crf_kernel<<<BB, 256>>>(start_t, end_t, trans, labels, lengths, out);
}